// round 1
// baseline (speedup 1.0000x reference)
#include <cuda_runtime.h>
#include <cuda_bf16.h>
#include <stdint.h>

#define Nn 100000
#define Ee 1600000
#define FEAT 32
#define EMB 32
#define Hh 64
#define Gg 128

// ---- device scratch (no allocations allowed) ----
__device__ float g_deg[Nn];
__device__ float g_dinv[Nn];
__device__ float g_norm[Ee];
__device__ float g_h[Nn * Hh];    // current node features (64)
__device__ float g_hw[Nn * Hh];   // h @ W
__device__ float g_acc[Nn * Hh];  // scatter accumulator

__device__ __forceinline__ void red_add_v4(float* addr, float a, float b, float c, float d) {
    asm volatile("red.global.add.v4.f32 [%0], {%1,%2,%3,%4};"
                 :: "l"(addr), "f"(a), "f"(b), "f"(c), "f"(d) : "memory");
}

// deg = 1.0 (self loop weight)
__global__ void k_init_deg() {
    int i = blockIdx.x * blockDim.x + threadIdx.x;
    if (i < Nn) g_deg[i] = 1.0f;
}

// deg[dst] += w[e]
__global__ void k_deg_scatter(const int* __restrict__ ei, const float* __restrict__ ew) {
    int e = blockIdx.x * blockDim.x + threadIdx.x;
    if (e < Ee) {
        int dst = ei[Ee + e];
        atomicAdd(&g_deg[dst], ew[e]);
    }
}

__global__ void k_dinv() {
    int i = blockIdx.x * blockDim.x + threadIdx.x;
    if (i < Nn) {
        float d = g_deg[i];
        g_dinv[i] = (d > 0.0f) ? rsqrtf(d) : 0.0f;
    }
}

__global__ void k_norm(const int* __restrict__ ei, const float* __restrict__ ew) {
    int e = blockIdx.x * blockDim.x + threadIdx.x;
    if (e < Ee) {
        int s = ei[e];
        int d = ei[Ee + e];
        g_norm[e] = g_dinv[s] * ew[e] * g_dinv[d];
    }
}

// h0 = concat(x, emb[mapping]) ; 16 float4 per node (8 from x, 8 from emb row)
__global__ void k_embed(const float* __restrict__ x, const int* __restrict__ mapping,
                        const float* __restrict__ emb) {
    int idx = blockIdx.x * blockDim.x + threadIdx.x;
    if (idx >= Nn * 16) return;
    int node = idx >> 4;
    int q = idx & 15;
    float4 v;
    if (q < 8) {
        v = reinterpret_cast<const float4*>(x)[node * 8 + q];
    } else {
        int m = mapping[node];
        v = reinterpret_cast<const float4*>(emb)[m * 8 + (q - 8)];
    }
    reinterpret_cast<float4*>(g_h)[node * 16 + q] = v;
}

// hw = h @ W  (64x64). One block = 64 rows. Shared: W tile + h tile.
__global__ void k_gemm(const float* __restrict__ W) {
    __shared__ float sW[64][64];
    __shared__ float sH[64][64];
    int tid = threadIdx.x;                 // 256 threads
    int rowBase = blockIdx.x * 64;
    // load W
    #pragma unroll
    for (int i = 0; i < 16; i++) {
        int t = tid + i * 256;
        sW[t >> 6][t & 63] = W[t];
    }
    // load h tile
    #pragma unroll
    for (int i = 0; i < 16; i++) {
        int t = tid + i * 256;
        int r = t >> 6;
        int gr = rowBase + r;
        sH[r][t & 63] = (gr < Nn) ? g_h[gr * 64 + (t & 63)] : 0.0f;
    }
    __syncthreads();
    int c = tid & 63;
    int r0 = tid >> 6;   // 0..3
    #pragma unroll
    for (int rr = 0; rr < 16; rr++) {
        int r = rr * 4 + r0;
        int gr = rowBase + r;
        if (gr >= Nn) continue;
        float acc = 0.0f;
        #pragma unroll
        for (int k = 0; k < 64; k++) acc += sH[r][k] * sW[k][c];
        g_hw[gr * 64 + c] = acc;
    }
}

// acc = dinv^2 * hw   (self-loop contribution; also initializes acc)
__global__ void k_selfinit() {
    int idx = blockIdx.x * blockDim.x + threadIdx.x;
    if (idx < Nn * Hh) {
        float s = g_dinv[idx >> 6];
        g_acc[idx] = s * s * g_hw[idx];
    }
}

// acc[dst] += norm[e] * hw[src], 16 threads/edge, vector red
__global__ void k_scatter(const int* __restrict__ ei) {
    long long idx = (long long)blockIdx.x * blockDim.x + threadIdx.x;
    if (idx >= (long long)Ee * 16) return;
    int e = (int)(idx >> 4);
    int lane = (int)(idx & 15);
    int src = ei[e];
    int dst = ei[Ee + e];
    float nrm = g_norm[e];
    float4 v = reinterpret_cast<const float4*>(g_hw)[src * 16 + lane];
    red_add_v4(&g_acc[dst * 64 + lane * 4], nrm * v.x, nrm * v.y, nrm * v.z, nrm * v.w);
}

// h = relu(acc + b)
__global__ void k_bias_relu(const float* __restrict__ b) {
    int idx = blockIdx.x * blockDim.x + threadIdx.x;
    if (idx < Nn * Hh) {
        float v = g_acc[idx] + b[idx & 63];
        g_h[idx] = v > 0.0f ? v : 0.0f;
    }
}

// mean pool: batch is sorted; one block per graph, binary search for segment
__global__ void k_pool(const int* __restrict__ batch, float* __restrict__ out) {
    __shared__ float sh[4][64];
    int g = blockIdx.x;
    int tid = threadIdx.x;   // 256
    // lower_bound(batch, g) and lower_bound(batch, g+1)
    int lo = 0, hi = Nn;
    while (lo < hi) { int mid = (lo + hi) >> 1; if (batch[mid] < g) lo = mid + 1; else hi = mid; }
    int start = lo;
    lo = start; hi = Nn;
    while (lo < hi) { int mid = (lo + hi) >> 1; if (batch[mid] < g + 1) lo = mid + 1; else hi = mid; }
    int end = lo;
    int c = tid & 63;
    int r = tid >> 6;  // 0..3
    float acc = 0.0f;
    for (int node = start + r; node < end; node += 4)
        acc += g_h[node * 64 + c];
    sh[r][c] = acc;
    __syncthreads();
    if (r == 0) {
        float s = sh[0][c] + sh[1][c] + sh[2][c] + sh[3][c];
        float cnt = (float)(end - start);
        out[g * 64 + c] = s / fmaxf(cnt, 1.0f);
    }
}

extern "C" void kernel_launch(void* const* d_in, const int* in_sizes, int n_in,
                              void* d_out, int out_size) {
    const float* x       = (const float*)d_in[0];
    const int*   mapping = (const int*)d_in[1];
    const int*   ei      = (const int*)d_in[2];
    const float* ew      = (const float*)d_in[3];
    const int*   batch   = (const int*)d_in[4];
    const float* emb     = (const float*)d_in[5];
    const float* W0      = (const float*)d_in[6];
    const float* b0      = (const float*)d_in[7];
    const float* W1      = (const float*)d_in[8];
    const float* b1      = (const float*)d_in[9];
    float* out = (float*)d_out;

    const int T = 256;
    // degree + norm
    k_init_deg<<<(Nn + T - 1) / T, T>>>();
    k_deg_scatter<<<(Ee + T - 1) / T, T>>>(ei, ew);
    k_dinv<<<(Nn + T - 1) / T, T>>>();
    k_norm<<<(Ee + T - 1) / T, T>>>(ei, ew);
    // features
    k_embed<<<(Nn * 16 + T - 1) / T, T>>>(x, mapping, emb);

    // layer 0
    k_gemm<<<(Nn + 63) / 64, T>>>(W0);
    k_selfinit<<<(Nn * Hh + T - 1) / T, T>>>();
    {
        long long total = (long long)Ee * 16;
        int blocks = (int)((total + T - 1) / T);
        k_scatter<<<blocks, T>>>(ei);
    }
    k_bias_relu<<<(Nn * Hh + T - 1) / T, T>>>(b0);

    // layer 1
    k_gemm<<<(Nn + 63) / 64, T>>>(W1);
    k_selfinit<<<(Nn * Hh + T - 1) / T, T>>>();
    {
        long long total = (long long)Ee * 16;
        int blocks = (int)((total + T - 1) / T);
        k_scatter<<<blocks, T>>>(ei);
    }
    k_bias_relu<<<(Nn * Hh + T - 1) / T, T>>>(b1);

    // pool
    k_pool<<<Gg, T>>>(batch, out);
}

// round 2
// speedup vs baseline: 1.3397x; 1.3397x over previous
#include <cuda_runtime.h>
#include <cuda_bf16.h>
#include <stdint.h>

#define Nn 100000
#define Ee 1600000
#define Hh 64
#define Gg 128
#define SCAN_BLK 1024
#define NSCAN ((Nn + SCAN_BLK - 1) / SCAN_BLK)   // 98

// ---- device scratch ----
__device__ float g_deg[Nn];
__device__ float g_dinv[Nn];
__device__ int   g_hist[Nn];
__device__ int   g_rowptr[Nn + 1];
__device__ int   g_wptr[Nn];
__device__ int   g_part[NSCAN];      // exclusive block offsets
__device__ int2  g_csr[Ee];          // {src, bitcast(norm)}
__device__ float g_h[Nn * Hh];
__device__ float g_hw[Nn * Hh];

// zero hist, deg=1 (self-loop weight), rowptr[Nn]=Ee
__global__ void k_zero() {
    int i = blockIdx.x * blockDim.x + threadIdx.x;
    if (i < Nn) { g_hist[i] = 0; g_deg[i] = 1.0f; }
    if (i == 0) g_rowptr[Nn] = Ee;
}

// histogram of dst + weighted degree
__global__ void k_hist(const int* __restrict__ ei, const float* __restrict__ ew) {
    int e = blockIdx.x * blockDim.x + threadIdx.x;
    if (e < Ee) {
        int dst = ei[Ee + e];
        atomicAdd(&g_hist[dst], 1);
        atomicAdd(&g_deg[dst], ew[e]);
    }
}

__global__ void k_dinv() {
    int i = blockIdx.x * blockDim.x + threadIdx.x;
    if (i < Nn) {
        float d = g_deg[i];
        g_dinv[i] = (d > 0.0f) ? rsqrtf(d) : 0.0f;
    }
}

// per-block sums of hist
__global__ void k_scan1() {
    __shared__ int wsum[32];
    int t = threadIdx.x, b = blockIdx.x;
    int i = b * SCAN_BLK + t;
    int v = (i < Nn) ? g_hist[i] : 0;
    // warp reduce
    for (int o = 16; o > 0; o >>= 1) v += __shfl_down_sync(0xffffffffu, v, o);
    if ((t & 31) == 0) wsum[t >> 5] = v;
    __syncthreads();
    if (t < 32) {
        int s = wsum[t];
        for (int o = 16; o > 0; o >>= 1) s += __shfl_down_sync(0xffffffffu, s, o);
        if (t == 0) g_part[b] = s;
    }
}

// exclusive scan of NSCAN partials (single block, 128 threads)
__global__ void k_scan2() {
    __shared__ int s[128];
    int t = threadIdx.x;
    int v = (t < NSCAN) ? g_part[t] : 0;
    s[t] = v;
    __syncthreads();
    for (int o = 1; o < 128; o <<= 1) {
        int u = (t >= o) ? s[t - o] : 0;
        __syncthreads();
        s[t] += u;
        __syncthreads();
    }
    if (t < NSCAN) g_part[t] = s[t] - v;   // exclusive
}

// per-element exclusive scan, write rowptr & wptr
__global__ void k_scan3() {
    __shared__ int wsum[32];
    __shared__ int woff[32];
    int t = threadIdx.x, b = blockIdx.x;
    int lane = t & 31, wid = t >> 5;
    int i = b * SCAN_BLK + t;
    int v = (i < Nn) ? g_hist[i] : 0;
    int incl = v;
    for (int o = 1; o < 32; o <<= 1) {
        int u = __shfl_up_sync(0xffffffffu, incl, o);
        if (lane >= o) incl += u;
    }
    if (lane == 31) wsum[wid] = incl;
    __syncthreads();
    if (wid == 0) {
        int s = (lane < 32) ? wsum[lane] : 0;
        int si = s;
        for (int o = 1; o < 32; o <<= 1) {
            int u = __shfl_up_sync(0xffffffffu, si, o);
            if (lane >= o) si += u;
        }
        woff[lane] = si - s;   // exclusive warp offsets
    }
    __syncthreads();
    if (i < Nn) {
        int excl = g_part[b] + woff[wid] + (incl - v);
        g_rowptr[i] = excl;
        g_wptr[i] = excl;
    }
}

// place edges into CSR buckets with precomputed norm
__global__ void k_place(const int* __restrict__ ei, const float* __restrict__ ew) {
    int e = blockIdx.x * blockDim.x + threadIdx.x;
    if (e < Ee) {
        int s = ei[e];
        int d = ei[Ee + e];
        float nrm = g_dinv[s] * ew[e] * g_dinv[d];
        int slot = atomicAdd(&g_wptr[d], 1);
        g_csr[slot] = make_int2(s, __float_as_int(nrm));
    }
}

// layer-0 GEMM fused with concat(x, emb[mapping]); hw = h0 @ W
__global__ void k_gemm0(const float* __restrict__ x, const int* __restrict__ mapping,
                        const float* __restrict__ emb, const float* __restrict__ W) {
    __shared__ float sW[64][64];
    __shared__ float sH[64][65];
    int tid = threadIdx.x;   // 256
    int rowBase = blockIdx.x * 64;
    #pragma unroll
    for (int i = 0; i < 16; i++) {
        int t = tid + i * 256;
        sW[t >> 6][t & 63] = W[t];
    }
    // 64 rows x 16 float4 = 1024 vec loads
    #pragma unroll
    for (int i = 0; i < 4; i++) {
        int t = tid + i * 256;
        int r = t >> 4;          // 0..63
        int q = t & 15;          // 0..15
        int gr = rowBase + r;
        float4 v = make_float4(0.f, 0.f, 0.f, 0.f);
        if (gr < Nn) {
            if (q < 8) v = reinterpret_cast<const float4*>(x)[gr * 8 + q];
            else {
                int m = mapping[gr];
                v = reinterpret_cast<const float4*>(emb)[m * 8 + (q - 8)];
            }
        }
        sH[r][q * 4 + 0] = v.x; sH[r][q * 4 + 1] = v.y;
        sH[r][q * 4 + 2] = v.z; sH[r][q * 4 + 3] = v.w;
    }
    __syncthreads();
    int c = tid & 63;
    int r0 = tid >> 6;
    #pragma unroll
    for (int rr = 0; rr < 16; rr++) {
        int r = rr * 4 + r0;
        int gr = rowBase + r;
        if (gr >= Nn) continue;
        float acc = 0.0f;
        #pragma unroll
        for (int k = 0; k < 64; k++) acc += sH[r][k] * sW[k][c];
        g_hw[gr * 64 + c] = acc;
    }
}

// hw = g_h @ W
__global__ void k_gemm(const float* __restrict__ W) {
    __shared__ float sW[64][64];
    __shared__ float sH[64][65];
    int tid = threadIdx.x;
    int rowBase = blockIdx.x * 64;
    #pragma unroll
    for (int i = 0; i < 16; i++) {
        int t = tid + i * 256;
        sW[t >> 6][t & 63] = W[t];
    }
    #pragma unroll
    for (int i = 0; i < 4; i++) {
        int t = tid + i * 256;
        int r = t >> 4;
        int q = t & 15;
        int gr = rowBase + r;
        float4 v = make_float4(0.f, 0.f, 0.f, 0.f);
        if (gr < Nn) v = reinterpret_cast<const float4*>(g_h)[gr * 16 + q];
        sH[r][q * 4 + 0] = v.x; sH[r][q * 4 + 1] = v.y;
        sH[r][q * 4 + 2] = v.z; sH[r][q * 4 + 3] = v.w;
    }
    __syncthreads();
    int c = tid & 63;
    int r0 = tid >> 6;
    #pragma unroll
    for (int rr = 0; rr < 16; rr++) {
        int r = rr * 4 + r0;
        int gr = rowBase + r;
        if (gr >= Nn) continue;
        float acc = 0.0f;
        #pragma unroll
        for (int k = 0; k < 64; k++) acc += sH[r][k] * sW[k][c];
        g_hw[gr * 64 + c] = acc;
    }
}

// gather: one warp per node. h[n] = relu(dinv[n]^2*hw[n] + sum_e norm*hw[src] + b)
__global__ void k_gather(const float* __restrict__ b) {
    int warpInBlock = threadIdx.x >> 5;
    int lane = threadIdx.x & 31;
    int n = blockIdx.x * 8 + warpInBlock;
    if (n >= Nn) return;
    const float2* hw2 = reinterpret_cast<const float2*>(g_hw);
    float2 acc = hw2[n * 32 + lane];
    float s = g_dinv[n];
    float s2 = s * s;
    acc.x *= s2; acc.y *= s2;
    int e = g_rowptr[n];
    int end = g_rowptr[n + 1];
    for (; e < end; e++) {
        int2 sw = g_csr[e];                 // broadcast across warp
        float w = __int_as_float(sw.y);
        float2 v = hw2[sw.x * 32 + lane];
        acc.x += w * v.x;
        acc.y += w * v.y;
    }
    float2 bb = reinterpret_cast<const float2*>(b)[lane];
    acc.x += bb.x; acc.y += bb.y;
    acc.x = acc.x > 0.f ? acc.x : 0.f;
    acc.y = acc.y > 0.f ? acc.y : 0.f;
    reinterpret_cast<float2*>(g_h)[n * 32 + lane] = acc;
}

// mean pool (batch sorted): one block per graph
__global__ void k_pool(const int* __restrict__ batch, float* __restrict__ out) {
    __shared__ float sh[4][64];
    int g = blockIdx.x;
    int tid = threadIdx.x;
    int lo = 0, hi = Nn;
    while (lo < hi) { int mid = (lo + hi) >> 1; if (batch[mid] < g) lo = mid + 1; else hi = mid; }
    int start = lo;
    lo = start; hi = Nn;
    while (lo < hi) { int mid = (lo + hi) >> 1; if (batch[mid] < g + 1) lo = mid + 1; else hi = mid; }
    int end = lo;
    int c = tid & 63;
    int r = tid >> 6;
    float acc = 0.0f;
    for (int node = start + r; node < end; node += 4)
        acc += g_h[node * 64 + c];
    sh[r][c] = acc;
    __syncthreads();
    if (r == 0) {
        float su = sh[0][c] + sh[1][c] + sh[2][c] + sh[3][c];
        float cnt = (float)(end - start);
        out[g * 64 + c] = su / fmaxf(cnt, 1.0f);
    }
}

extern "C" void kernel_launch(void* const* d_in, const int* in_sizes, int n_in,
                              void* d_out, int out_size) {
    const float* x       = (const float*)d_in[0];
    const int*   mapping = (const int*)d_in[1];
    const int*   ei      = (const int*)d_in[2];
    const float* ew      = (const float*)d_in[3];
    const int*   batch   = (const int*)d_in[4];
    const float* emb     = (const float*)d_in[5];
    const float* W0      = (const float*)d_in[6];
    const float* b0      = (const float*)d_in[7];
    const float* W1      = (const float*)d_in[8];
    const float* b1      = (const float*)d_in[9];
    float* out = (float*)d_out;

    const int T = 256;
    // CSR build + norms
    k_zero<<<(Nn + T - 1) / T, T>>>();
    k_hist<<<(Ee + T - 1) / T, T>>>(ei, ew);
    k_dinv<<<(Nn + T - 1) / T, T>>>();
    k_scan1<<<NSCAN, SCAN_BLK>>>();
    k_scan2<<<1, 128>>>();
    k_scan3<<<NSCAN, SCAN_BLK>>>();
    k_place<<<(Ee + T - 1) / T, T>>>(ei, ew);

    // layer 0 (embed fused into gemm)
    k_gemm0<<<(Nn + 63) / 64, T>>>(x, mapping, emb, W0);
    k_gather<<<(Nn + 7) / 8, T>>>(b0);

    // layer 1
    k_gemm<<<(Nn + 63) / 64, T>>>(W1);
    k_gather<<<(Nn + 7) / 8, T>>>(b1);

    // pool
    k_pool<<<Gg, T>>>(batch, out);
}

// round 3
// speedup vs baseline: 2.4402x; 1.8214x over previous
#include <cuda_runtime.h>
#include <cuda_fp16.h>
#include <cuda_bf16.h>
#include <stdint.h>

#define Nn 100000
#define Ee 1600000
#define Hh 64
#define Gg 128
#define SCAN_BLK 1024
#define NSCAN ((Nn + SCAN_BLK - 1) / SCAN_BLK)   // 98

// ---- device scratch ----
__device__ float g_deg[Nn];
__device__ float g_dinv[Nn];
__device__ int   g_hist[Nn];
__device__ int   g_rowptr[Nn + 1];
__device__ int   g_wptr[Nn];
__device__ int   g_part[NSCAN];
__device__ int2  g_csr[Ee];           // {src, bitcast(norm)}
__device__ float g_h[Nn * Hh];        // fp32 node features
__device__ __half g_hw[Nn * Hh];      // h @ W in fp16 (gather input)

__global__ void k_zero() {
    int i = blockIdx.x * blockDim.x + threadIdx.x;
    if (i < Nn) { g_hist[i] = 0; g_deg[i] = 1.0f; }
    if (i == 0) g_rowptr[Nn] = Ee;
}

__global__ void k_hist(const int* __restrict__ ei, const float* __restrict__ ew) {
    int e = blockIdx.x * blockDim.x + threadIdx.x;
    if (e < Ee) {
        int dst = ei[Ee + e];
        atomicAdd(&g_hist[dst], 1);
        atomicAdd(&g_deg[dst], ew[e]);
    }
}

// block sums of hist + dinv computation (fused)
__global__ void k_scan1() {
    __shared__ int wsum[32];
    int t = threadIdx.x, b = blockIdx.x;
    int i = b * SCAN_BLK + t;
    int v = 0;
    if (i < Nn) {
        v = g_hist[i];
        float d = g_deg[i];
        g_dinv[i] = (d > 0.0f) ? rsqrtf(d) : 0.0f;
    }
    int s = v;
    for (int o = 16; o > 0; o >>= 1) s += __shfl_down_sync(0xffffffffu, s, o);
    if ((t & 31) == 0) wsum[t >> 5] = s;
    __syncthreads();
    if (t < 32) {
        int u = wsum[t];
        for (int o = 16; o > 0; o >>= 1) u += __shfl_down_sync(0xffffffffu, u, o);
        if (t == 0) g_part[b] = u;
    }
}

__global__ void k_scan2() {
    __shared__ int s[128];
    int t = threadIdx.x;
    int v = (t < NSCAN) ? g_part[t] : 0;
    s[t] = v;
    __syncthreads();
    for (int o = 1; o < 128; o <<= 1) {
        int u = (t >= o) ? s[t - o] : 0;
        __syncthreads();
        s[t] += u;
        __syncthreads();
    }
    if (t < NSCAN) g_part[t] = s[t] - v;
}

__global__ void k_scan3() {
    __shared__ int wsum[32];
    __shared__ int woff[32];
    int t = threadIdx.x, b = blockIdx.x;
    int lane = t & 31, wid = t >> 5;
    int i = b * SCAN_BLK + t;
    int v = (i < Nn) ? g_hist[i] : 0;
    int incl = v;
    for (int o = 1; o < 32; o <<= 1) {
        int u = __shfl_up_sync(0xffffffffu, incl, o);
        if (lane >= o) incl += u;
    }
    if (lane == 31) wsum[wid] = incl;
    __syncthreads();
    if (wid == 0) {
        int s = (lane < 32) ? wsum[lane] : 0;
        int si = s;
        for (int o = 1; o < 32; o <<= 1) {
            int u = __shfl_up_sync(0xffffffffu, si, o);
            if (lane >= o) si += u;
        }
        woff[lane] = si - s;
    }
    __syncthreads();
    if (i < Nn) {
        int excl = g_part[b] + woff[wid] + (incl - v);
        g_rowptr[i] = excl;
        g_wptr[i] = excl;
    }
}

__global__ void k_place(const int* __restrict__ ei, const float* __restrict__ ew) {
    int e = blockIdx.x * blockDim.x + threadIdx.x;
    if (e < Ee) {
        int s = ei[e];
        int d = ei[Ee + e];
        float nrm = g_dinv[s] * ew[e] * g_dinv[d];
        int slot = atomicAdd(&g_wptr[d], 1);
        g_csr[slot] = make_int2(s, __float_as_int(nrm));
    }
}

// ---- GEMM core: 64x64 tile, 256 threads, each thread 4 rows x 4 cols ----
__device__ __forceinline__ void gemm_compute(float (&sW)[64][64], float (&sH)[64][68],
                                             int rowBase, int tid) {
    int cq = tid & 15;         // col quad
    int rq = tid >> 4;         // row quad 0..15
    float acc[4][4];
    #pragma unroll
    for (int j = 0; j < 4; j++)
        #pragma unroll
        for (int i = 0; i < 4; i++) acc[j][i] = 0.0f;
    #pragma unroll
    for (int k = 0; k < 64; k++) {
        float4 w = *reinterpret_cast<float4*>(&sW[k][cq * 4]);
        #pragma unroll
        for (int j = 0; j < 4; j++) {
            float a = sH[rq * 4 + j][k];
            acc[j][0] += a * w.x;
            acc[j][1] += a * w.y;
            acc[j][2] += a * w.z;
            acc[j][3] += a * w.w;
        }
    }
    #pragma unroll
    for (int j = 0; j < 4; j++) {
        int gr = rowBase + rq * 4 + j;
        if (gr >= Nn) continue;
        __half2 p0 = __floats2half2_rn(acc[j][0], acc[j][1]);
        __half2 p1 = __floats2half2_rn(acc[j][2], acc[j][3]);
        __half2* dst = reinterpret_cast<__half2*>(&g_hw[gr * 64 + cq * 4]);
        dst[0] = p0;
        dst[1] = p1;
    }
}

// layer-0: concat(x, emb[mapping]) @ W0
__global__ void k_gemm0(const float* __restrict__ x, const int* __restrict__ mapping,
                        const float* __restrict__ emb, const float* __restrict__ W) {
    __shared__ float sW[64][64];
    __shared__ float sH[64][68];
    int tid = threadIdx.x;   // 256
    int rowBase = blockIdx.x * 64;
    #pragma unroll
    for (int i = 0; i < 4; i++) {
        int t = tid + i * 256;   // float4 index into W (1024 total)
        reinterpret_cast<float4*>(&sW[0][0])[ (t >> 4) * 17 * 0 + t ] = reinterpret_cast<const float4*>(W)[t];
    }
    #pragma unroll
    for (int i = 0; i < 4; i++) {
        int t = tid + i * 256;
        int r = t >> 4;
        int q = t & 15;
        int gr = rowBase + r;
        float4 v = make_float4(0.f, 0.f, 0.f, 0.f);
        if (gr < Nn) {
            if (q < 8) v = reinterpret_cast<const float4*>(x)[gr * 8 + q];
            else {
                int m = __ldg(&mapping[gr]);
                v = reinterpret_cast<const float4*>(emb)[m * 8 + (q - 8)];
            }
        }
        *reinterpret_cast<float4*>(&sH[r][q * 4]) = v;
    }
    __syncthreads();
    gemm_compute(sW, sH, rowBase, tid);
}

// hw = g_h @ W
__global__ void k_gemm(const float* __restrict__ W) {
    __shared__ float sW[64][64];
    __shared__ float sH[64][68];
    int tid = threadIdx.x;
    int rowBase = blockIdx.x * 64;
    #pragma unroll
    for (int i = 0; i < 4; i++) {
        int t = tid + i * 256;
        reinterpret_cast<float4*>(&sW[0][0])[t] = reinterpret_cast<const float4*>(W)[t];
    }
    #pragma unroll
    for (int i = 0; i < 4; i++) {
        int t = tid + i * 256;
        int r = t >> 4;
        int q = t & 15;
        int gr = rowBase + r;
        float4 v = make_float4(0.f, 0.f, 0.f, 0.f);
        if (gr < Nn) v = reinterpret_cast<const float4*>(g_h)[gr * 16 + q];
        *reinterpret_cast<float4*>(&sH[r][q * 4]) = v;
    }
    __syncthreads();
    gemm_compute(sW, sH, rowBase, tid);
}

// gather: one warp per node; hw rows are fp16 (128B)
__global__ void k_gather(const float* __restrict__ b) {
    int warpInBlock = threadIdx.x >> 5;
    int lane = threadIdx.x & 31;
    int n = blockIdx.x * 8 + warpInBlock;
    if (n >= Nn) return;
    const __half2* hw2 = reinterpret_cast<const __half2*>(g_hw);
    float2 self = __half22float2(hw2[n * 32 + lane]);
    float s = g_dinv[n];
    float s2 = s * s;
    float2 acc;
    acc.x = self.x * s2;
    acc.y = self.y * s2;
    int e = g_rowptr[n];
    int end = g_rowptr[n + 1];
    // 2x unrolled for MLP
    for (; e + 1 < end; e += 2) {
        int2 sw0 = __ldg(&g_csr[e]);
        int2 sw1 = __ldg(&g_csr[e + 1]);
        float2 v0 = __half22float2(hw2[sw0.x * 32 + lane]);
        float2 v1 = __half22float2(hw2[sw1.x * 32 + lane]);
        float w0 = __int_as_float(sw0.y);
        float w1 = __int_as_float(sw1.y);
        acc.x += w0 * v0.x + w1 * v1.x;
        acc.y += w0 * v0.y + w1 * v1.y;
    }
    if (e < end) {
        int2 sw = __ldg(&g_csr[e]);
        float w = __int_as_float(sw.y);
        float2 v = __half22float2(hw2[sw.x * 32 + lane]);
        acc.x += w * v.x;
        acc.y += w * v.y;
    }
    float2 bb = reinterpret_cast<const float2*>(b)[lane];
    acc.x += bb.x; acc.y += bb.y;
    acc.x = acc.x > 0.f ? acc.x : 0.f;
    acc.y = acc.y > 0.f ? acc.y : 0.f;
    reinterpret_cast<float2*>(g_h)[n * 32 + lane] = acc;
}

__global__ void k_pool(const int* __restrict__ batch, float* __restrict__ out) {
    __shared__ float sh[4][64];
    int g = blockIdx.x;
    int tid = threadIdx.x;
    int lo = 0, hi = Nn;
    while (lo < hi) { int mid = (lo + hi) >> 1; if (batch[mid] < g) lo = mid + 1; else hi = mid; }
    int start = lo;
    lo = start; hi = Nn;
    while (lo < hi) { int mid = (lo + hi) >> 1; if (batch[mid] < g + 1) lo = mid + 1; else hi = mid; }
    int end = lo;
    int c = tid & 63;
    int r = tid >> 6;
    float acc = 0.0f;
    for (int node = start + r; node < end; node += 4)
        acc += g_h[node * 64 + c];
    sh[r][c] = acc;
    __syncthreads();
    if (r == 0) {
        float su = sh[0][c] + sh[1][c] + sh[2][c] + sh[3][c];
        float cnt = (float)(end - start);
        out[g * 64 + c] = su / fmaxf(cnt, 1.0f);
    }
}

extern "C" void kernel_launch(void* const* d_in, const int* in_sizes, int n_in,
                              void* d_out, int out_size) {
    const float* x       = (const float*)d_in[0];
    const int*   mapping = (const int*)d_in[1];
    const int*   ei      = (const int*)d_in[2];
    const float* ew      = (const float*)d_in[3];
    const int*   batch   = (const int*)d_in[4];
    const float* emb     = (const float*)d_in[5];
    const float* W0      = (const float*)d_in[6];
    const float* b0      = (const float*)d_in[7];
    const float* W1      = (const float*)d_in[8];
    const float* b1      = (const float*)d_in[9];
    float* out = (float*)d_out;

    const int T = 256;
    k_zero<<<(Nn + T - 1) / T, T>>>();
    k_hist<<<(Ee + T - 1) / T, T>>>(ei, ew);
    k_scan1<<<NSCAN, SCAN_BLK>>>();
    k_scan2<<<1, 128>>>();
    k_scan3<<<NSCAN, SCAN_BLK>>>();
    k_place<<<(Ee + T - 1) / T, T>>>(ei, ew);

    k_gemm0<<<(Nn + 63) / 64, T>>>(x, mapping, emb, W0);
    k_gather<<<(Nn + 7) / 8, T>>>(b0);

    k_gemm<<<(Nn + 63) / 64, T>>>(W1);
    k_gather<<<(Nn + 7) / 8, T>>>(b1);

    k_pool<<<Gg, T>>>(batch, out);
}

// round 4
// speedup vs baseline: 2.5468x; 1.0437x over previous
#include <cuda_runtime.h>
#include <cuda_fp16.h>
#include <cuda_bf16.h>
#include <stdint.h>

#define Nn 100000
#define Ee 1600000
#define Hh 64
#define Gg 128
#define SCAN_BLK 1024
#define NSCAN ((Nn + SCAN_BLK - 1) / SCAN_BLK)   // 98

struct ND { int cnt; float deg; };

// ---- device scratch ----
__device__ ND    g_nd[Nn];
__device__ float g_dinv[Nn];
__device__ int   g_rowptr[Nn + 1];
__device__ int   g_wptr[Nn];
__device__ int   g_part[NSCAN];
__device__ int2  g_csr[Ee];            // {src, bitcast(norm)}
__device__ __half g_h[Nn * Hh];        // node features (fp16)
__device__ __half g_hw[Nn * Hh];       // h @ W (fp16, gather input)

__global__ void k_zero() {
    int i = blockIdx.x * blockDim.x + threadIdx.x;
    if (i < Nn) { g_nd[i].cnt = 0; g_nd[i].deg = 1.0f; }
    if (i == 0) g_rowptr[Nn] = Ee;
}

__global__ void k_hist(const int* __restrict__ ei, const float* __restrict__ ew) {
    int e = blockIdx.x * blockDim.x + threadIdx.x;
    if (e < Ee) {
        int dst = ei[Ee + e];
        atomicAdd(&g_nd[dst].cnt, 1);
        atomicAdd(&g_nd[dst].deg, ew[e]);
    }
}

// block sums of cnt + dinv (fused)
__global__ void k_scan1() {
    __shared__ int wsum[32];
    int t = threadIdx.x, b = blockIdx.x;
    int i = b * SCAN_BLK + t;
    int v = 0;
    if (i < Nn) {
        ND nd = g_nd[i];
        v = nd.cnt;
        g_dinv[i] = (nd.deg > 0.0f) ? rsqrtf(nd.deg) : 0.0f;
    }
    int s = v;
    for (int o = 16; o > 0; o >>= 1) s += __shfl_down_sync(0xffffffffu, s, o);
    if ((t & 31) == 0) wsum[t >> 5] = s;
    __syncthreads();
    if (t < 32) {
        int u = wsum[t];
        for (int o = 16; o > 0; o >>= 1) u += __shfl_down_sync(0xffffffffu, u, o);
        if (t == 0) g_part[b] = u;
    }
}

// per-element exclusive scan; each block also scans the 98 partials locally
__global__ void k_scan3() {
    __shared__ int sp[128];
    __shared__ int wsum[32];
    __shared__ int woff[32];
    int t = threadIdx.x, b = blockIdx.x;
    int lane = t & 31, wid = t >> 5;

    if (t < 128) sp[t] = (t < NSCAN) ? g_part[t] : 0;
    __syncthreads();
    #pragma unroll
    for (int o = 1; o < 128; o <<= 1) {
        int u = 0;
        if (t < 128 && t >= o) u = sp[t - o];
        __syncthreads();
        if (t < 128) sp[t] += u;
        __syncthreads();
    }
    int blockOff = (b > 0) ? sp[b - 1] : 0;

    int i = b * SCAN_BLK + t;
    int v = (i < Nn) ? g_nd[i].cnt : 0;
    int incl = v;
    for (int o = 1; o < 32; o <<= 1) {
        int u = __shfl_up_sync(0xffffffffu, incl, o);
        if (lane >= o) incl += u;
    }
    if (lane == 31) wsum[wid] = incl;
    __syncthreads();
    if (wid == 0) {
        int s = (lane < 32) ? wsum[lane] : 0;
        int si = s;
        for (int o = 1; o < 32; o <<= 1) {
            int u = __shfl_up_sync(0xffffffffu, si, o);
            if (lane >= o) si += u;
        }
        woff[lane] = si - s;
    }
    __syncthreads();
    if (i < Nn) {
        int excl = blockOff + woff[wid] + (incl - v);
        g_rowptr[i] = excl;
        g_wptr[i] = excl;
    }
}

__global__ void k_place(const int* __restrict__ ei, const float* __restrict__ ew) {
    int e = blockIdx.x * blockDim.x + threadIdx.x;
    if (e < Ee) {
        int s = ei[e];
        int d = ei[Ee + e];
        float nrm = g_dinv[s] * ew[e] * g_dinv[d];
        int slot = atomicAdd(&g_wptr[d], 1);
        g_csr[slot] = make_int2(s, __float_as_int(nrm));
    }
}

// ---- layer-0 GEMM: concat(x, emb[mapping]) @ W0  (fp32 inputs) ----
__global__ void k_gemm0(const float* __restrict__ x, const int* __restrict__ mapping,
                        const float* __restrict__ emb, const float* __restrict__ W) {
    __shared__ float sW[64][64];
    __shared__ float sH[64][68];
    int tid = threadIdx.x;   // 256
    int rowBase = blockIdx.x * 64;
    #pragma unroll
    for (int i = 0; i < 4; i++) {
        int t = tid + i * 256;
        reinterpret_cast<float4*>(&sW[0][0])[t] = reinterpret_cast<const float4*>(W)[t];
    }
    #pragma unroll
    for (int i = 0; i < 4; i++) {
        int t = tid + i * 256;
        int r = t >> 4;
        int q = t & 15;
        int gr = rowBase + r;
        float4 v = make_float4(0.f, 0.f, 0.f, 0.f);
        if (gr < Nn) {
            if (q < 8) v = reinterpret_cast<const float4*>(x)[gr * 8 + q];
            else {
                int m = __ldg(&mapping[gr]);
                v = reinterpret_cast<const float4*>(emb)[m * 8 + (q - 8)];
            }
        }
        *reinterpret_cast<float4*>(&sH[r][q * 4]) = v;
    }
    __syncthreads();
    int cq = tid & 15;
    int rq = tid >> 4;
    float acc[4][4];
    #pragma unroll
    for (int j = 0; j < 4; j++)
        #pragma unroll
        for (int i = 0; i < 4; i++) acc[j][i] = 0.0f;
    #pragma unroll
    for (int k = 0; k < 64; k++) {
        float4 w = *reinterpret_cast<float4*>(&sW[k][cq * 4]);
        #pragma unroll
        for (int j = 0; j < 4; j++) {
            float a = sH[rq * 4 + j][k];
            acc[j][0] += a * w.x;
            acc[j][1] += a * w.y;
            acc[j][2] += a * w.z;
            acc[j][3] += a * w.w;
        }
    }
    #pragma unroll
    for (int j = 0; j < 4; j++) {
        int gr = rowBase + rq * 4 + j;
        if (gr >= Nn) continue;
        __half2* dst = reinterpret_cast<__half2*>(&g_hw[gr * 64 + cq * 4]);
        dst[0] = __floats2half2_rn(acc[j][0], acc[j][1]);
        dst[1] = __floats2half2_rn(acc[j][2], acc[j][3]);
    }
}

// ---- layer-1 GEMM: g_h (fp16) @ W1 ----
__global__ void k_gemm1(const float* __restrict__ W) {
    __shared__ float sW[64][64];
    __shared__ __half2 sH[64][36];   // 32 half2 per row + pad
    int tid = threadIdx.x;
    int rowBase = blockIdx.x * 64;
    #pragma unroll
    for (int i = 0; i < 4; i++) {
        int t = tid + i * 256;
        reinterpret_cast<float4*>(&sW[0][0])[t] = reinterpret_cast<const float4*>(W)[t];
    }
    // 64 rows x 8 (half2 x4 =16B) loads: 512 uint4 loads
    #pragma unroll
    for (int i = 0; i < 2; i++) {
        int t = tid + i * 256;       // 0..511
        int r = t >> 3;              // 0..63
        int q = t & 7;               // 0..7 (16B chunks)
        int gr = rowBase + r;
        uint4 v = make_uint4(0, 0, 0, 0);
        if (gr < Nn) v = reinterpret_cast<const uint4*>(g_h)[gr * 8 + q];
        *reinterpret_cast<uint4*>(&sH[r][q * 4]) = v;
    }
    __syncthreads();
    int cq = tid & 15;
    int rq = tid >> 4;
    float acc[4][4];
    #pragma unroll
    for (int j = 0; j < 4; j++)
        #pragma unroll
        for (int i = 0; i < 4; i++) acc[j][i] = 0.0f;
    #pragma unroll
    for (int k2 = 0; k2 < 32; k2++) {
        float4 w0 = *reinterpret_cast<float4*>(&sW[2 * k2][cq * 4]);
        float4 w1 = *reinterpret_cast<float4*>(&sW[2 * k2 + 1][cq * 4]);
        #pragma unroll
        for (int j = 0; j < 4; j++) {
            float2 a = __half22float2(sH[rq * 4 + j][k2]);
            acc[j][0] += a.x * w0.x + a.y * w1.x;
            acc[j][1] += a.x * w0.y + a.y * w1.y;
            acc[j][2] += a.x * w0.z + a.y * w1.z;
            acc[j][3] += a.x * w0.w + a.y * w1.w;
        }
    }
    #pragma unroll
    for (int j = 0; j < 4; j++) {
        int gr = rowBase + rq * 4 + j;
        if (gr >= Nn) continue;
        __half2* dst = reinterpret_cast<__half2*>(&g_hw[gr * 64 + cq * 4]);
        dst[0] = __floats2half2_rn(acc[j][0], acc[j][1]);
        dst[1] = __floats2half2_rn(acc[j][2], acc[j][3]);
    }
}

// gather: one warp per node; h output in fp16
__global__ void k_gather(const float* __restrict__ b) {
    int warpInBlock = threadIdx.x >> 5;
    int lane = threadIdx.x & 31;
    int n = blockIdx.x * 8 + warpInBlock;
    if (n >= Nn) return;
    const __half2* hw2 = reinterpret_cast<const __half2*>(g_hw);
    float2 self = __half22float2(hw2[n * 32 + lane]);
    float s = g_dinv[n];
    float s2 = s * s;
    float2 acc;
    acc.x = self.x * s2;
    acc.y = self.y * s2;
    int e = g_rowptr[n];
    int end = g_rowptr[n + 1];
    for (; e + 1 < end; e += 2) {
        int2 sw0 = __ldg(&g_csr[e]);
        int2 sw1 = __ldg(&g_csr[e + 1]);
        float2 v0 = __half22float2(hw2[sw0.x * 32 + lane]);
        float2 v1 = __half22float2(hw2[sw1.x * 32 + lane]);
        float w0 = __int_as_float(sw0.y);
        float w1 = __int_as_float(sw1.y);
        acc.x += w0 * v0.x + w1 * v1.x;
        acc.y += w0 * v0.y + w1 * v1.y;
    }
    if (e < end) {
        int2 sw = __ldg(&g_csr[e]);
        float w = __int_as_float(sw.y);
        float2 v = __half22float2(hw2[sw.x * 32 + lane]);
        acc.x += w * v.x;
        acc.y += w * v.y;
    }
    float2 bb = reinterpret_cast<const float2*>(b)[lane];
    acc.x += bb.x; acc.y += bb.y;
    acc.x = acc.x > 0.f ? acc.x : 0.f;
    acc.y = acc.y > 0.f ? acc.y : 0.f;
    reinterpret_cast<__half2*>(g_h)[n * 32 + lane] = __floats2half2_rn(acc.x, acc.y);
}

// mean pool (batch sorted): one block per graph; h is fp16
__global__ void k_pool(const int* __restrict__ batch, float* __restrict__ out) {
    __shared__ float sh[8][64];
    int g = blockIdx.x;
    int tid = threadIdx.x;   // 256
    int lo = 0, hi = Nn;
    while (lo < hi) { int mid = (lo + hi) >> 1; if (batch[mid] < g) lo = mid + 1; else hi = mid; }
    int start = lo;
    lo = start; hi = Nn;
    while (lo < hi) { int mid = (lo + hi) >> 1; if (batch[mid] < g + 1) lo = mid + 1; else hi = mid; }
    int end = lo;
    int c2 = tid & 31;       // half2 column (0..31)
    int r = tid >> 5;        // 0..7
    const __half2* h2 = reinterpret_cast<const __half2*>(g_h);
    float2 acc = make_float2(0.f, 0.f);
    for (int node = start + r; node < end; node += 8) {
        float2 v = __half22float2(h2[node * 32 + c2]);
        acc.x += v.x; acc.y += v.y;
    }
    sh[r][c2 * 2] = acc.x;
    sh[r][c2 * 2 + 1] = acc.y;
    __syncthreads();
    if (r == 0) {
        int c = tid;   // 0..63? only threads 0..63 of warp-pair; use c2 mapping:
    }
    // reduce 8 partials for both columns handled by this thread pair
    if (tid < 64) {
        float su = 0.f;
        #pragma unroll
        for (int k = 0; k < 8; k++) su += sh[k][tid];
        float cnt = (float)(end - start);
        out[g * 64 + tid] = su / fmaxf(cnt, 1.0f);
    }
}

extern "C" void kernel_launch(void* const* d_in, const int* in_sizes, int n_in,
                              void* d_out, int out_size) {
    const float* x       = (const float*)d_in[0];
    const int*   mapping = (const int*)d_in[1];
    const int*   ei      = (const int*)d_in[2];
    const float* ew      = (const float*)d_in[3];
    const int*   batch   = (const int*)d_in[4];
    const float* emb     = (const float*)d_in[5];
    const float* W0      = (const float*)d_in[6];
    const float* b0      = (const float*)d_in[7];
    const float* W1      = (const float*)d_in[8];
    const float* b1      = (const float*)d_in[9];
    float* out = (float*)d_out;

    const int T = 256;
    k_zero<<<(Nn + T - 1) / T, T>>>();
    k_hist<<<(Ee + T - 1) / T, T>>>(ei, ew);
    k_scan1<<<NSCAN, SCAN_BLK>>>();
    k_scan3<<<NSCAN, SCAN_BLK>>>();
    k_place<<<(Ee + T - 1) / T, T>>>(ei, ew);

    k_gemm0<<<(Nn + 63) / 64, T>>>(x, mapping, emb, W0);
    k_gather<<<(Nn + 7) / 8, T>>>(b0);

    k_gemm1<<<(Nn + 63) / 64, T>>>(W1);
    k_gather<<<(Nn + 7) / 8, T>>>(b1);

    k_pool<<<Gg, T>>>(batch, out);
}